// round 14
// baseline (speedup 1.0000x reference)
#include <cuda_runtime.h>
#include <math_constants.h>

#define NTOK 2304      // 48*48
#define CDIM 256
#define BSZ  4
#define NH   8
#define HD   32
#define SCALE 0.17677669529663687f   // 32^-0.5

typedef unsigned long long u64;
__device__ __forceinline__ u64 pk2(float lo, float hi) {
    u64 r; asm("mov.b64 %0,{%1,%2};" : "=l"(r) : "f"(lo), "f"(hi)); return r;
}
__device__ __forceinline__ void upk2(u64 v, float& lo, float& hi) {
    asm("mov.b64 {%0,%1},%2;" : "=f"(lo), "=f"(hi) : "l"(v));
}
__device__ __forceinline__ void fma2(u64& d, u64 a, u64 b) {
    asm("fma.rn.f32x2 %0,%1,%2,%0;" : "+l"(d) : "l"(a), "l"(b));
}
__device__ __forceinline__ void mul2(u64& d, u64 a) {
    asm("mul.rn.f32x2 %0,%0,%1;" : "+l"(d) : "l"(a));
}

// ---------------- scratch ----------------
__device__ float g_Q [2][BSZ*NH*NTOK*HD];   // (b,h,n,d)
__device__ float g_Kt[2][BSZ*NH*HD*NTOK];   // (b,h,d,n)
__device__ float g_V [2][BSZ*NH*NTOK*HD];   // (b,h,n,d)
__device__ float g_AttO[2][BSZ*NTOK*CDIM];  // (b,n,c)

// ---------------- fused QKV projection (4 GEMMs, one launch) — unchanged ----------------
__global__ void __launch_bounds__(256) proj_qkv_fused(
    const float* __restrict__ img, const float* __restrict__ radar,
    const float* __restrict__ Wq_img, const float* __restrict__ Wkv_radar,
    const float* __restrict__ Wq_radar, const float* __restrict__ Wkv_img)
{
    const int zz  = blockIdx.z;
    const int seg = zz >> 2;
    const int b   = zz & 3;
    const float* X; const float* W; int ncol, kind, attn;
    switch (seg) {
        case 0:  X = img;   W = Wq_img;    ncol = CDIM;     kind = 0; attn = 0; break;
        case 1:  X = radar; W = Wkv_radar; ncol = 2 * CDIM; kind = 1; attn = 0; break;
        case 2:  X = radar; W = Wq_radar;  ncol = CDIM;     kind = 0; attn = 1; break;
        default: X = img;   W = Wkv_img;   ncol = 2 * CDIM; kind = 1; attn = 1; break;
    }
    const int n0 = blockIdx.y * 64;
    if (n0 >= ncol) return;
    const int m0 = blockIdx.x * 64;

    __shared__ __align__(16) float2 Asd[16][64];
    __shared__ __align__(16) float  Bs [16][64];

    const int tid = threadIdx.x;
    const int tx = tid & 15, ty = tid >> 4;
    const float* Xb = X + (size_t)b * CDIM * NTOK;

    u64 acc2[4][2] = {};
    for (int k0 = 0; k0 < CDIM; k0 += 16) {
        #pragma unroll
        for (int i = tid; i < 16 * 64; i += 256) {
            int k = i >> 6, m = i & 63;
            float v = Xb[(size_t)(k0 + k) * NTOK + m0 + m];
            Asd[k][m] = make_float2(v, v);
        }
        #pragma unroll
        for (int i = tid; i < 16 * 64; i += 256) {
            int k = i >> 6, n = i & 63;
            Bs[k][n] = W[(size_t)(k0 + k) * ncol + n0 + n];
        }
        __syncthreads();
        #pragma unroll
        for (int k = 0; k < 16; k++) {
            ulonglong2 a01 = *(const ulonglong2*)&Asd[k][ty * 4];
            ulonglong2 a23 = *(const ulonglong2*)&Asd[k][ty * 4 + 2];
            ulonglong2 bb  = *(const ulonglong2*)&Bs[k][tx * 4];
            fma2(acc2[0][0], a01.x, bb.x); fma2(acc2[0][1], a01.x, bb.y);
            fma2(acc2[1][0], a01.y, bb.x); fma2(acc2[1][1], a01.y, bb.y);
            fma2(acc2[2][0], a23.x, bb.x); fma2(acc2[2][1], a23.x, bb.y);
            fma2(acc2[3][0], a23.y, bb.x); fma2(acc2[3][1], a23.y, bb.y);
        }
        __syncthreads();
    }

    float acc[4][4];
    #pragma unroll
    for (int i = 0; i < 4; i++)
        #pragma unroll
        for (int p = 0; p < 2; p++)
            upk2(acc2[i][p], acc[i][2*p], acc[i][2*p+1]);

    float* oQ  = g_Q[attn];
    float* oKt = g_Kt[attn];
    float* oV  = g_V[attn];
    #pragma unroll
    for (int i = 0; i < 4; i++) {
        int n = m0 + ty * 4 + i;
        #pragma unroll
        for (int j = 0; j < 4; j++) {
            int cp = n0 + tx * 4 + j;
            float v = acc[i][j];
            if (kind == 0) {
                int h = cp >> 5, d = cp & 31;
                oQ[(((size_t)b * NH + h) * NTOK + n) * HD + d] = v;
            } else {
                if (cp < CDIM) {
                    int h = cp >> 5, d = cp & 31;
                    oKt[(((size_t)b * NH + h) * HD + d) * NTOK + n] = v;
                } else {
                    int c2 = cp - CDIM;
                    int h = c2 >> 5, d = c2 & 31;
                    oV[(((size_t)b * NH + h) * NTOK + n) * HD + d] = v;
                }
            }
        }
    }
}

// ---------------- attention: dup-V PV (zero packs), dynamic smem ----------------
// grid (NTOK/64, BSZ*NH, 2), block 256 = 16x16.
// dynamic smem layout (all offsets 16B-aligned):
//   Qs  float [32][68]  @ 0       (8704 B)  pre-scaled, padded (col-writes)
//   Ks  float [32][64]  @ 8704    (8192 B)  row-contiguous only
//   Vsd float2[64][32]  @ 16896   (16384 B) dup pairs
//   Ps  float [64][68]  @ 33280   (17408 B)
//   tws float [64]      @ 50688   (256 B)
#define SMEM_ATTN 50944
__global__ void __launch_bounds__(256) attn_kernel(const float* __restrict__ umask)
{
    extern __shared__ __align__(16) char smem_raw[];
    float  (*Qs)[68]  = (float (*)[68]) (smem_raw);
    float  (*Ks)[64]  = (float (*)[64]) (smem_raw + 8704);
    float2 (*Vsd)[32] = (float2(*)[32])(smem_raw + 16896);
    float  (*Ps)[68]  = (float (*)[68]) (smem_raw + 33280);
    float*  tws       = (float*)        (smem_raw + 50688);

    const int attn = blockIdx.z;
    const int bh   = blockIdx.y;
    const int b    = bh >> 3;
    const int h    = bh & 7;
    const int row0 = blockIdx.x * 64;

    const float* Q  = g_Q[attn];
    const float* Kt = g_Kt[attn];
    const float* V  = g_V[attn];

    const int tid = threadIdx.x;
    const int tx  = tid & 15;
    const int ty  = tid >> 4;

    if (tid < 64) {
        int n = row0 + tid;
        float f = SCALE;
        if (attn == 0) f *= 1.0f / (umask[(size_t)b * NTOK + n] + 1e-6f);
        tws[tid] = f;
    }
    __syncthreads();

    #pragma unroll
    for (int i = tid; i < 64 * HD; i += 256) {
        int m = i >> 5, d = i & 31;
        Qs[d][m] = Q[((size_t)bh * NTOK + row0 + m) * HD + d] * tws[m];
    }

    const size_t ktbase = (size_t)bh * HD * NTOK;
    const size_t vbase  = (size_t)bh * NTOK * HD;

    float runm[4], denom[4];
    #pragma unroll
    for (int i = 0; i < 4; i++) { runm[i] = -CUDART_INF_F; denom[i] = 0.f; }
    u64 oacc[2][2] = {};   // [rowpair][d]

    for (int kb = 0; kb < NTOK; kb += 64) {
        __syncthreads();
        // K staging: 32 rows x 64 cols, float4 (2 per thread)
        #pragma unroll
        for (int i = tid; i < 512; i += 256) {
            int d = i >> 4, jq = i & 15;
            *(float4*)&Ks[d][jq * 4] =
                *(const float4*)&Kt[ktbase + (size_t)d * NTOK + kb + jq * 4];
        }
        // V staging: 64 rows x 32 cols, load float4, store dup pairs (2x STS.128)
        #pragma unroll
        for (int i = tid; i < 512; i += 256) {
            int j = i >> 3, dq = i & 7;
            float4 v = *(const float4*)&V[vbase + (size_t)(kb + j) * HD + dq * 4];
            *(float4*)&Vsd[j][dq * 4]     = make_float4(v.x, v.x, v.y, v.y);
            *(float4*)&Vsd[j][dq * 4 + 2] = make_float4(v.z, v.z, v.w, v.w);
        }
        __syncthreads();

        // ---- S = Qs^T Ks : 4x4 microtile, row-pair packed ----
        u64 sacc[2][4] = {};
        #pragma unroll
        for (int d = 0; d < HD; d++) {
            ulonglong2 av = *(const ulonglong2*)&Qs[d][ty * 4];   // native row-pairs
            float4 bk = *(const float4*)&Ks[d][tx * 4];
            u64 b0 = pk2(bk.x, bk.x), b1 = pk2(bk.y, bk.y);
            u64 b2 = pk2(bk.z, bk.z), b3 = pk2(bk.w, bk.w);
            fma2(sacc[0][0], av.x, b0); fma2(sacc[1][0], av.y, b0);
            fma2(sacc[0][1], av.x, b1); fma2(sacc[1][1], av.y, b1);
            fma2(sacc[0][2], av.x, b2); fma2(sacc[1][2], av.y, b2);
            fma2(sacc[0][3], av.x, b3); fma2(sacc[1][3], av.y, b3);
        }

        float s[4][4];
        #pragma unroll
        for (int p = 0; p < 2; p++)
            #pragma unroll
            for (int j = 0; j < 4; j++)
                upk2(sacc[p][j], s[2*p][j], s[2*p+1][j]);

        // ---- online softmax (row reduce over 16 tx lanes) ----
        float corrv[4];
        #pragma unroll
        for (int i = 0; i < 4; i++) {
            float mloc = fmaxf(fmaxf(s[i][0], s[i][1]), fmaxf(s[i][2], s[i][3]));
            #pragma unroll
            for (int o = 8; o > 0; o >>= 1)
                mloc = fmaxf(mloc, __shfl_xor_sync(0xffffffffu, mloc, o));
            float nm = fmaxf(runm[i], mloc);
            float corr = __expf(runm[i] - nm);
            float psum = 0.f;
            #pragma unroll
            for (int j = 0; j < 4; j++) {
                float pe = __expf(s[i][j] - nm);
                s[i][j] = pe;
                psum += pe;
            }
            #pragma unroll
            for (int o = 8; o > 0; o >>= 1)
                psum += __shfl_xor_sync(0xffffffffu, psum, o);
            denom[i] = denom[i] * corr + psum;
            runm[i] = nm;
            corrv[i] = corr;
        }
        u64 c0 = pk2(corrv[0], corrv[1]);
        u64 c1 = pk2(corrv[2], corrv[3]);
        mul2(oacc[0][0], c0); mul2(oacc[0][1], c0);
        mul2(oacc[1][0], c1); mul2(oacc[1][1], c1);

        #pragma unroll
        for (int jj = 0; jj < 4; jj++)
            *(float4*)&Ps[tx * 4 + jj][ty * 4] =
                make_float4(s[0][jj], s[1][jj], s[2][jj], s[3][jj]);
        __syncthreads();

        // ---- O += P * V : native P row-pairs, dup-V dims — zero packs ----
        #pragma unroll 16
        for (int j = 0; j < 64; j++) {
            ulonglong2 pv = *(const ulonglong2*)&Ps[j][ty * 4];    // {P0,P1},{P2,P3}
            ulonglong2 vv = *(const ulonglong2*)&Vsd[j][tx * 2];   // dup d0, dup d1
            fma2(oacc[0][0], pv.x, vv.x); fma2(oacc[1][0], pv.y, vv.x);
            fma2(oacc[0][1], pv.x, vv.y); fma2(oacc[1][1], pv.y, vv.y);
        }
    }

    float o[4][2];
    #pragma unroll
    for (int p = 0; p < 2; p++)
        #pragma unroll
        for (int dd = 0; dd < 2; dd++)
            upk2(oacc[p][dd], o[2*p][dd], o[2*p+1][dd]);

    #pragma unroll
    for (int i = 0; i < 4; i++) {
        float rinv = 1.0f / denom[i];
        int n = row0 + ty * 4 + i;
        #pragma unroll
        for (int dd = 0; dd < 2; dd++)
            g_AttO[attn][((size_t)b * NTOK + n) * CDIM + h * HD + tx * 2 + dd] =
                o[i][dd] * rinv;
    }
}

// ---------------- fused output projection (both modalities) — unchanged ----------------
__global__ void __launch_bounds__(256) proj_out_fused(
    const float* __restrict__ Wp_img, const float* __restrict__ bp_img,
    const float* __restrict__ Wp_radar, const float* __restrict__ bp_radar,
    float* __restrict__ out)
{
    const int zz = blockIdx.z;
    const int which = zz >> 2;
    const int b     = zz & 3;
    const float* Wp = which ? Wp_radar : Wp_img;
    const float* bp = which ? bp_radar : bp_img;
    float* outw = out + (size_t)which * BSZ * CDIM * NTOK;

    __shared__ __align__(16) float2 Asd[16][66];
    __shared__ __align__(16) float  Bs [16][64];
    const int m0 = blockIdx.x * 64;
    const int n0 = blockIdx.y * 64;
    const int tid = threadIdx.x;
    const int tx = tid & 15, ty = tid >> 4;
    const float* A = g_AttO[which] + (size_t)b * NTOK * CDIM;

    u64 acc2[4][2] = {};
    for (int k0 = 0; k0 < CDIM; k0 += 16) {
        #pragma unroll
        for (int i = tid; i < 16 * 64; i += 256) {
            int m = i >> 4, k = i & 15;
            float v = A[(size_t)(m0 + m) * CDIM + k0 + k];
            Asd[k][m] = make_float2(v, v);
        }
        #pragma unroll
        for (int i = tid; i < 16 * 64; i += 256) {
            int k = i >> 6, n = i & 63;
            Bs[k][n] = Wp[(size_t)(k0 + k) * CDIM + n0 + n];
        }
        __syncthreads();
        #pragma unroll
        for (int k = 0; k < 16; k++) {
            ulonglong2 a01 = *(const ulonglong2*)&Asd[k][ty * 4];
            ulonglong2 a23 = *(const ulonglong2*)&Asd[k][ty * 4 + 2];
            ulonglong2 bb  = *(const ulonglong2*)&Bs[k][tx * 4];
            fma2(acc2[0][0], a01.x, bb.x); fma2(acc2[0][1], a01.x, bb.y);
            fma2(acc2[1][0], a01.y, bb.x); fma2(acc2[1][1], a01.y, bb.y);
            fma2(acc2[2][0], a23.x, bb.x); fma2(acc2[2][1], a23.x, bb.y);
            fma2(acc2[3][0], a23.y, bb.x); fma2(acc2[3][1], a23.y, bb.y);
        }
        __syncthreads();
    }

    float acc[4][4];
    #pragma unroll
    for (int i = 0; i < 4; i++)
        #pragma unroll
        for (int p = 0; p < 2; p++)
            upk2(acc2[i][p], acc[i][2*p], acc[i][2*p+1]);

    float* outb = outw + (size_t)b * CDIM * NTOK;
    #pragma unroll
    for (int j = 0; j < 4; j++) {
        int cp = n0 + tx * 4 + j;
        float bias = bp[cp];
        #pragma unroll
        for (int i = 0; i < 4; i++) {
            int n = m0 + ty * 4 + i;
            outb[(size_t)cp * NTOK + n] = acc[i][j] + bias;
        }
    }
}

// ---------------- launch ----------------
extern "C" void kernel_launch(void* const* d_in, const int* in_sizes, int n_in,
                              void* d_out, int out_size)
{
    const float* img   = (const float*)d_in[0];
    const float* radar = (const float*)d_in[1];
    const float* umask = (const float*)d_in[2];
    const float* Wq_img    = (const float*)d_in[3];
    const float* Wkv_radar = (const float*)d_in[4];
    const float* Wq_radar  = (const float*)d_in[5];
    const float* Wkv_img   = (const float*)d_in[6];
    const float* Wp_img    = (const float*)d_in[7];
    const float* bp_img    = (const float*)d_in[8];
    const float* Wp_radar  = (const float*)d_in[9];
    const float* bp_radar  = (const float*)d_in[10];
    float* out = (float*)d_out;

    cudaFuncSetAttribute(attn_kernel,
                         cudaFuncAttributeMaxDynamicSharedMemorySize, SMEM_ATTN);

    dim3 gP(NTOK / 64, 8, 16);
    proj_qkv_fused<<<gP, 256>>>(img, radar, Wq_img, Wkv_radar, Wq_radar, Wkv_img);

    dim3 gA(NTOK / 64, BSZ * NH, 2);
    attn_kernel<<<gA, 256, SMEM_ATTN>>>(umask);

    dim3 gO(NTOK / 64, CDIM / 64, 8);
    proj_out_fused<<<gO, 256>>>(Wp_img, bp_img, Wp_radar, bp_radar, out);
}